// round 2
// baseline (speedup 1.0000x reference)
#include <cuda_runtime.h>
#include <cstdint>

// Problem constants (fixed shapes)
#define LXC 4096
#define LZC 4096
#define DAC 1024
#define SCALE 0.03125f        // 1/sqrt(1024)
#define NEG_MASKED (-31.25f)  // -1000 * SCALE (mask fill applied BEFORE scaling)

// Scratch (device globals: allocation-guard safe)
__device__ float g_q[(size_t)DAC * LXC];
__device__ float g_k[(size_t)DAC * LZC];
__device__ float g_v[(size_t)DAC * LZC];
__device__ float g_s[(size_t)LZC * LXC];
__device__ int   g_mask_is_word;   // 1 if mask is int32 0/1, 0 if byte mask

// ---------------------------------------------------------------------------
// Mask dtype detection: scan first 4096 uint32 words. If mask is byte-packed
// bool, words contain packed 0/1 bytes -> values like 0x00010100 > 1 appear
// with overwhelming probability. If int32, all words are 0 or 1.
// ---------------------------------------------------------------------------
__global__ void detect_mask_kernel(const unsigned int* __restrict__ mw) {
    __shared__ int flag;
    if (threadIdx.x == 0) flag = 1;
    __syncthreads();
    bool byte_like = false;
    for (int i = threadIdx.x; i < 4096; i += 256)
        if (mw[i] > 1u) byte_like = true;
    if (byte_like) flag = 0;   // benign same-value race
    __syncthreads();
    if (threadIdx.x == 0) g_mask_is_word = flag;
}

// ---------------------------------------------------------------------------
// SGEMM: C(MxN) = op(A) @ B [+ bias]  (all row-major, dims multiples of 128)
//   TRANS_A=0: A is (M,K) row-major.      TRANS_A=1: A is (K,M) row-major (TN).
//   EPI=0: C = acc + bias[row] (bias may be null)
//   EPI=1: masked score epilogue: C = mask ? acc*SCALE : NEG_MASKED
// Block tile 128x128, K-tile 16, 256 threads, 8x8 per thread (4+4 split).
// ---------------------------------------------------------------------------
template <int TRANS_A, int EPI>
__global__ __launch_bounds__(256, 2)
void sgemm_kernel(const float* __restrict__ A, const float* __restrict__ B,
                  float* __restrict__ C, int M, int N, int K,
                  const float* __restrict__ bias,
                  const void* __restrict__ mask)
{
    constexpr int BM = 128, BN = 128, BK = 16;
    __shared__ float As[BK][BM];
    __shared__ float Bs[BK][BN];

    const int tid = threadIdx.x;
    const int m0 = blockIdx.y * BM;
    const int n0 = blockIdx.x * BN;
    const int tx = tid & 15;   // 0..15 -> N
    const int ty = tid >> 4;   // 0..15 -> M

    float acc[8][8];
#pragma unroll
    for (int i = 0; i < 8; i++)
#pragma unroll
        for (int j = 0; j < 8; j++) acc[i][j] = 0.0f;

    for (int k0 = 0; k0 < K; k0 += BK) {
        // ---- load A tile ----
#pragma unroll
        for (int v = 0; v < 2; v++) {
            int vec = tid + v * 256;              // 512 float4 loads total
            if (TRANS_A) {
                // A is (K,M): tile rows = k, cols = m. Fully coalesced.
                int r = vec >> 5;                 // 0..15
                int c = (vec & 31) << 2;          // 0..124
                float4 a = *(const float4*)(A + (size_t)(k0 + r) * M + m0 + c);
                *(float4*)&As[r][c] = a;
            } else {
                // A is (M,K): tile rows = m (128), cols = k (16). Transpose on store.
                int r = vec >> 2;                 // 0..127
                int s = vec & 3;                  // 0..3 (4-float segment)
                float4 a = *(const float4*)(A + (size_t)(m0 + r) * K + k0 + s * 4);
                As[s * 4 + 0][r] = a.x;
                As[s * 4 + 1][r] = a.y;
                As[s * 4 + 2][r] = a.z;
                As[s * 4 + 3][r] = a.w;
            }
            // ---- load B tile (K,N): fully coalesced ----
            int rb = vec >> 5;
            int cb = (vec & 31) << 2;
            float4 b = *(const float4*)(B + (size_t)(k0 + rb) * N + n0 + cb);
            *(float4*)&Bs[rb][cb] = b;
        }
        __syncthreads();

        // ---- compute ----
#pragma unroll
        for (int kk = 0; kk < BK; kk++) {
            float4 a0 = *(const float4*)&As[kk][ty * 4];
            float4 a1 = *(const float4*)&As[kk][64 + ty * 4];
            float4 b0 = *(const float4*)&Bs[kk][tx * 4];
            float4 b1 = *(const float4*)&Bs[kk][64 + tx * 4];
            float ra[8] = {a0.x, a0.y, a0.z, a0.w, a1.x, a1.y, a1.z, a1.w};
            float rb2[8] = {b0.x, b0.y, b0.z, b0.w, b1.x, b1.y, b1.z, b1.w};
#pragma unroll
            for (int i = 0; i < 8; i++)
#pragma unroll
                for (int j = 0; j < 8; j++)
                    acc[i][j] = fmaf(ra[i], rb2[j], acc[i][j]);
        }
        __syncthreads();
    }

    // ---- epilogue ----
    int rows[8], cols[8];
#pragma unroll
    for (int t = 0; t < 4; t++) {
        rows[t]     = m0 + ty * 4 + t;
        rows[4 + t] = m0 + 64 + ty * 4 + t;
        cols[t]     = n0 + tx * 4 + t;
        cols[4 + t] = n0 + 64 + tx * 4 + t;
    }

    if (EPI == 0) {
#pragma unroll
        for (int i = 0; i < 8; i++) {
            float bval = bias ? bias[rows[i]] : 0.0f;
#pragma unroll
            for (int j = 0; j < 8; j++)
                C[(size_t)rows[i] * N + cols[j]] = acc[i][j] + bval;
        }
    } else {
        const int is_word = g_mask_is_word;
#pragma unroll
        for (int i = 0; i < 8; i++) {
#pragma unroll
            for (int j = 0; j < 8; j++) {
                size_t idx = (size_t)rows[i] * N + cols[j];
                bool mset = is_word
                    ? (((const int*)mask)[idx] != 0)
                    : (((const unsigned char*)mask)[idx] != 0);
                C[idx] = mset ? acc[i][j] * SCALE : NEG_MASKED;
            }
        }
    }
}

// ---------------------------------------------------------------------------
// In-place softmax over dim 0 (rows, lz) of S (LZ, LX) row-major.
// lane = column -> coalesced 128B/warp per row. 32 columns per block,
// 8 row-strips per column, shared reduction.
// ---------------------------------------------------------------------------
__global__ __launch_bounds__(256)
void softmax_kernel(float* __restrict__ S) {
    __shared__ float red[8][32];
    const int lane = threadIdx.x & 31;
    const int ty = threadIdx.x >> 5;           // 0..7
    const int col = blockIdx.x * 32 + lane;

    float m = -1e30f;
#pragma unroll 4
    for (int r = ty; r < LZC; r += 8)
        m = fmaxf(m, S[(size_t)r * LXC + col]);
    red[ty][lane] = m;
    __syncthreads();
#pragma unroll
    for (int j = 0; j < 8; j++) m = fmaxf(m, red[j][lane]);
    __syncthreads();

    float sum = 0.0f;
#pragma unroll 4
    for (int r = ty; r < LZC; r += 8)
        sum += __expf(S[(size_t)r * LXC + col] - m);
    red[ty][lane] = sum;
    __syncthreads();
    sum = 0.0f;
#pragma unroll
    for (int j = 0; j < 8; j++) sum += red[j][lane];
    const float inv = 1.0f / sum;

#pragma unroll 4
    for (int r = ty; r < LZC; r += 8) {
        size_t idx = (size_t)r * LXC + col;
        S[idx] = __expf(S[idx] - m) * inv;
    }
}

// ---------------------------------------------------------------------------
// Launch: q = Wq@X+bq; k = Wk@Z+bk; v = Wv@Z+bv;
//         s = mask_scale(k^T q); softmax cols; out = v @ s
// ---------------------------------------------------------------------------
extern "C" void kernel_launch(void* const* d_in, const int* in_sizes, int n_in,
                              void* d_out, int out_size) {
    const float* X    = (const float*)d_in[0];
    const float* Z    = (const float*)d_in[1];
    const void*  mask = d_in[2];
    const float* Wq   = (const float*)d_in[3];
    const float* bq   = (const float*)d_in[4];
    const float* Wk   = (const float*)d_in[5];
    const float* bk   = (const float*)d_in[6];
    const float* Wv   = (const float*)d_in[7];
    const float* bv   = (const float*)d_in[8];
    float* out = (float*)d_out;

    float *q, *k, *v, *s;
    cudaGetSymbolAddress((void**)&q, g_q);
    cudaGetSymbolAddress((void**)&k, g_k);
    cudaGetSymbolAddress((void**)&v, g_v);
    cudaGetSymbolAddress((void**)&s, g_s);

    detect_mask_kernel<<<1, 256>>>((const unsigned int*)mask);

    // q, k, v projections: (1024 x 1024) @ (1024 x 4096)
    sgemm_kernel<0, 0><<<dim3(LXC / 128, DAC / 128), 256>>>(Wq, X, q, DAC, LXC, DAC, bq, nullptr);
    sgemm_kernel<0, 0><<<dim3(LZC / 128, DAC / 128), 256>>>(Wk, Z, k, DAC, LZC, DAC, bk, nullptr);
    sgemm_kernel<0, 0><<<dim3(LZC / 128, DAC / 128), 256>>>(Wv, Z, v, DAC, LZC, DAC, bv, nullptr);

    // score (lz, lx) = k^T @ q, fused mask + scale
    sgemm_kernel<1, 1><<<dim3(LXC / 128, LZC / 128), 256>>>(k, q, s, LZC, LXC, DAC, nullptr, mask);

    // softmax over lz (in place)
    softmax_kernel<<<LXC / 32, 256>>>(s);

    // out (dout, lx) = v @ attn
    sgemm_kernel<0, 0><<<dim3(LXC / 128, DAC / 128), 256>>>(v, s, out, DAC, LXC, LZC, nullptr, nullptr);
}

// round 4
// speedup vs baseline: 2.6528x; 2.6528x over previous
#include <cuda_runtime.h>
#include <cuda_bf16.h>
#include <cstdint>

#define LXC 4096
#define LZC 4096
#define DAC 1024
#define SCALE 0.03125f        // 1/sqrt(1024)
#define NEG_MASKED (-31.25f)  // -1000 * SCALE (fill applied BEFORE scaling)

// ---------------------------------------------------------------------------
// Device-global scratch. Packed operands are stored as the exact SW128-
// swizzled smem tile image: tiles of 128 rows x 64 bf16 cols (16384 B),
// tile (panel p, chunk c) at offset (p*NC + c)*16384.
// ---------------------------------------------------------------------------
__device__ __align__(256) __nv_bfloat16 g_XTp_h[(size_t)LXC * DAC], g_XTp_l[(size_t)LXC * DAC];
__device__ __align__(256) __nv_bfloat16 g_ZTp_h[(size_t)LZC * DAC], g_ZTp_l[(size_t)LZC * DAC];
__device__ __align__(256) __nv_bfloat16 g_Wqp_h[(size_t)DAC * DAC], g_Wqp_l[(size_t)DAC * DAC];
__device__ __align__(256) __nv_bfloat16 g_Wkp_h[(size_t)DAC * DAC], g_Wkp_l[(size_t)DAC * DAC];
__device__ __align__(256) __nv_bfloat16 g_Wvp_h[(size_t)DAC * DAC], g_Wvp_l[(size_t)DAC * DAC];
__device__ __align__(256) __nv_bfloat16 g_qTp_h[(size_t)LXC * DAC], g_qTp_l[(size_t)LXC * DAC];
__device__ __align__(256) __nv_bfloat16 g_kTp_h[(size_t)LZC * DAC], g_kTp_l[(size_t)LZC * DAC];
__device__ __align__(256) __nv_bfloat16 g_vp_h[(size_t)DAC * LZC],  g_vp_l[(size_t)DAC * LZC];
__device__ __align__(256) __nv_bfloat16 g_aTp_h[(size_t)LXC * LZC], g_aTp_l[(size_t)LXC * LZC];
__device__ __align__(256) float         g_ST[(size_t)LXC * LZC];
__device__ __align__(256) unsigned char g_maskT[(size_t)LXC * LZC];
__device__ int g_mask_is_word;

// ---------------------------------------------------------------------------
// PTX helpers (all non-"a" features: sm_80/sm_90 baseline)
// ---------------------------------------------------------------------------
__device__ __forceinline__ uint32_t elect_one_pred() {
    uint32_t pred;
    asm volatile("{\n\t.reg .pred p;\n\t"
                 "elect.sync _|p, 0xFFFFFFFF;\n\t"
                 "selp.b32 %0, 1, 0, p;\n\t}" : "=r"(pred));
    return pred;
}
__device__ __forceinline__ uint32_t smem_u32(const void* p) {
    uint32_t a;
    asm("{ .reg .u64 t; cvta.to.shared.u64 t, %1; cvt.u32.u64 %0, t; }" : "=r"(a) : "l"(p));
    return a;
}

#define MBARRIER_INIT(mb, cnt) \
    asm volatile("mbarrier.init.shared.b64 [%0], %1;" \
                 :: "r"((uint32_t)(mb)), "r"((uint32_t)(cnt)) : "memory")
#define MBARRIER_INVAL(mb) \
    asm volatile("mbarrier.inval.shared.b64 [%0];" :: "r"((uint32_t)(mb)) : "memory")
#define MBARRIER_EXPECT_TX(mb, tx) \
    asm volatile("mbarrier.arrive.expect_tx.shared.b64 _, [%0], %1;" \
                 :: "r"((uint32_t)(mb)), "r"((uint32_t)(tx)) : "memory")

#define MBARRIER_WAIT_PARITY(mb, par) do {                                        \
    uint32_t _m = (uint32_t)(mb); uint32_t _p = (uint32_t)(par); uint32_t _d;     \
    asm volatile("{\n\t.reg .pred p;\n\t"                                         \
        "mbarrier.try_wait.parity.acquire.cta.shared::cta.b64 p, [%1], %2;\n\t"   \
        "selp.b32 %0, 1, 0, p;\n\t}" : "=r"(_d) : "r"(_m), "r"(_p) : "memory");   \
    if (!_d) {                                                                    \
        asm volatile("{\n\t.reg .pred P1;\n\t"                                    \
            "WAIT_LOOP_%=:\n\t"                                                   \
            "mbarrier.try_wait.parity.acquire.cta.shared::cta.b64 P1, [%0], %1, 0x989680;\n\t" \
            "@P1 bra.uni WAIT_DONE_%=;\n\t"                                       \
            "bra.uni WAIT_LOOP_%=;\n\t"                                           \
            "WAIT_DONE_%=:\n\t}" :: "r"(_m), "r"(_p) : "memory");                 \
    }                                                                             \
} while (0)

#define SWZ128(bo) ((bo) ^ (((bo) >> 3) & 0x70))

__device__ __forceinline__ void bulk_g2s(uint32_t dst, const void* src,
                                         uint32_t bytes, uint32_t mbar) {
    asm volatile(
        "cp.async.bulk.shared::cluster.global.mbarrier::complete_tx::bytes [%0], [%1], %2, [%3];"
        :: "r"(dst), "l"(src), "r"(bytes), "r"(mbar) : "memory");
}

__device__ __forceinline__ void ldsm4(uint32_t* d, uint32_t addr) {
    asm volatile("ldmatrix.sync.aligned.m8n8.x4.shared.b16 {%0,%1,%2,%3}, [%4];"
                 : "=r"(d[0]), "=r"(d[1]), "=r"(d[2]), "=r"(d[3]) : "r"(addr));
}

__device__ __forceinline__ void mma16816(float* c, const uint32_t* a, const uint32_t* b) {
    asm volatile("mma.sync.aligned.m16n8k16.row.col.f32.bf16.bf16.f32 "
        "{%0,%1,%2,%3}, {%4,%5,%6,%7}, {%8,%9}, {%0,%1,%2,%3};"
        : "+f"(c[0]), "+f"(c[1]), "+f"(c[2]), "+f"(c[3])
        : "r"(a[0]), "r"(a[1]), "r"(a[2]), "r"(a[3]), "r"(b[0]), "r"(b[1]));
}

// split fp32 -> bf16 hi/lo; pack 8 values; store 16B hi + 16B lo
__device__ __forceinline__ void split8_store(const float* fv, char* dh, char* dl) {
    uint32_t hw[4], lw[4];
#pragma unroll
    for (int j = 0; j < 4; j++) {
        __nv_bfloat16 h0 = __float2bfloat16(fv[2 * j]);
        __nv_bfloat16 h1 = __float2bfloat16(fv[2 * j + 1]);
        __nv_bfloat16 l0 = __float2bfloat16(fv[2 * j]     - __bfloat162float(h0));
        __nv_bfloat16 l1 = __float2bfloat16(fv[2 * j + 1] - __bfloat162float(h1));
        hw[j] = (uint32_t)__bfloat16_as_ushort(h0) | ((uint32_t)__bfloat16_as_ushort(h1) << 16);
        lw[j] = (uint32_t)__bfloat16_as_ushort(l0) | ((uint32_t)__bfloat16_as_ushort(l1) << 16);
    }
    *(uint4*)dh = make_uint4(hw[0], hw[1], hw[2], hw[3]);
    *(uint4*)dl = make_uint4(lw[0], lw[1], lw[2], lw[3]);
}

// ---------------------------------------------------------------------------
// HMMA GEMM: C[m,n] = sum_k (Ah+Al)[m,k]*(Bh+Bl)[n,k] (3-product, fp32 acc)
// A,B are packed swizzled-tile images. 128x128 CTA tile, K-chunk 64,
// 8 warps (warp tile 32x64), mma.sync.m16n8k16 bf16.
// EPI 0: +bias[n], packed split-bf16 out.  EPI 1: +bias[m], packed split out.
// EPI 2: mask+scale (maskT row-major), fp32 out.  EPI 3: plain fp32 out.
// ---------------------------------------------------------------------------
#define GEMM_SMEM 134144
#define CS_LD 132   // fp32 epilogue staging row stride (pad vs bank conflicts)

template <int EPI>
__global__ __launch_bounds__(256, 1)
void mma_gemm(const __nv_bfloat16* __restrict__ Ah, const __nv_bfloat16* __restrict__ Al,
              const __nv_bfloat16* __restrict__ Bh, const __nv_bfloat16* __restrict__ Bl,
              int NC,
              float* __restrict__ Cf, __nv_bfloat16* __restrict__ Ch,
              __nv_bfloat16* __restrict__ Cl, int NCout, int ldc,
              const float* __restrict__ bias, const unsigned char* __restrict__ maskT)
{
    extern __shared__ char smem[];
    const uint32_t sb = smem_u32(smem);
    const int tid = threadIdx.x, wid = tid >> 5, lane = tid & 31;
    const int pm = blockIdx.y, pn = blockIdx.x;
    const int m0 = pm * 128, n0 = pn * 128;
    const uint32_t stg = (sb + 2048 + 1023) & ~1023u;   // 2 stages x 64KB
    char* stgp = smem + (stg - sb);
    const uint32_t mb_full[2] = {sb + 16, sb + 24};
    float* sbias = (float*)(smem + 512);

    if (tid == 0) { MBARRIER_INIT(mb_full[0], 1); MBARRIER_INIT(mb_full[1], 1); }
    if (EPI == 0 && tid < 128) sbias[tid] = bias[n0 + tid];
    __syncthreads();

    int leader = 0;
    if (wid == 0) leader = elect_one_pred();

    const char* aHb = (const char*)Ah + (size_t)pm * NC * 16384;
    const char* aLb = (const char*)Al + (size_t)pm * NC * 16384;
    const char* bHb = (const char*)Bh + (size_t)pn * NC * 16384;
    const char* bLb = (const char*)Bl + (size_t)pn * NC * 16384;

    auto prefetch = [&](int c, int b) {
        MBARRIER_EXPECT_TX(mb_full[b], 65536u);
        uint32_t d = stg + ((uint32_t)b << 16);
        size_t off = (size_t)c * 16384;
        bulk_g2s(d,         aHb + off, 16384u, mb_full[b]);
        bulk_g2s(d + 16384, aLb + off, 16384u, mb_full[b]);
        bulk_g2s(d + 32768, bHb + off, 16384u, mb_full[b]);
        bulk_g2s(d + 49152, bLb + off, 16384u, mb_full[b]);
    };
    if (leader) { prefetch(0, 0); prefetch(1, 1); }

    // warp tiling: 4 warps over M (32 rows each), 2 warps over N (64 cols each)
    const int mbase = (wid & 3) * 32;
    const int nbase = (wid >> 2) * 64;
    const int r8 = lane & 7, g = lane >> 3;

    // lane-invariant row byte offsets
    uint32_t arow[2], brow[4];
#pragma unroll
    for (int tm = 0; tm < 2; tm++)
        arow[tm] = (uint32_t)(mbase + tm * 16 + (g & 1) * 8 + r8) * 128u;
#pragma unroll
    for (int tp = 0; tp < 4; tp++)
        brow[tp] = (uint32_t)(nbase + tp * 16 + (g >> 1) * 8 + r8) * 128u;
    const uint32_t kbA = (uint32_t)(g >> 1) * 16u;
    const uint32_t kbB = (uint32_t)(g & 1) * 16u;

    float cacc[2][8][4];
#pragma unroll
    for (int i = 0; i < 2; i++)
#pragma unroll
        for (int j = 0; j < 8; j++)
#pragma unroll
            for (int e = 0; e < 4; e++) cacc[i][j][e] = 0.0f;

    int fp0 = 0, fp1 = 0;
    for (int c = 0; c < NC; c++) {
        const int b = c & 1;
        if (b) { MBARRIER_WAIT_PARITY(mb_full[1], fp1); fp1 ^= 1; }
        else   { MBARRIER_WAIT_PARITY(mb_full[0], fp0); fp0 ^= 1; }
        const uint32_t base = stg + ((uint32_t)b << 16);

#pragma unroll
        for (int ks = 0; ks < 4; ks++) {
            const uint32_t kb = (uint32_t)ks * 32u;
            uint32_t ah[2][4], al[2][4], bh[8][2], bl[8][2];
#pragma unroll
            for (int tm = 0; tm < 2; tm++) {
                uint32_t sw = SWZ128(arow[tm] + kb + kbA);
                ldsm4(ah[tm], base + sw);
                ldsm4(al[tm], base + 16384u + sw);
            }
#pragma unroll
            for (int tp = 0; tp < 4; tp++) {
                uint32_t sw = SWZ128(brow[tp] + kb + kbB);
                uint32_t t[4];
                ldsm4(t, base + 32768u + sw);
                bh[2 * tp][0] = t[0]; bh[2 * tp][1] = t[1];
                bh[2 * tp + 1][0] = t[2]; bh[2 * tp + 1][1] = t[3];
                ldsm4(t, base + 49152u + sw);
                bl[2 * tp][0] = t[0]; bl[2 * tp][1] = t[1];
                bl[2 * tp + 1][0] = t[2]; bl[2 * tp + 1][1] = t[3];
            }
#pragma unroll
            for (int tm = 0; tm < 2; tm++)
#pragma unroll
                for (int tn = 0; tn < 8; tn++) {
                    mma16816(cacc[tm][tn], ah[tm], bh[tn]);
                    mma16816(cacc[tm][tn], ah[tm], bl[tn]);
                    mma16816(cacc[tm][tn], al[tm], bh[tn]);
                }
        }
        __syncthreads();
        if (leader && c + 2 < NC) prefetch(c + 2, b);
    }

    // ---- stage accumulators to smem fp32 (reuse stage region) ----
    float* cs = (float*)stgp;
#pragma unroll
    for (int tm = 0; tm < 2; tm++)
#pragma unroll
        for (int tn = 0; tn < 8; tn++) {
            int row = mbase + tm * 16 + (lane >> 2);
            int col = nbase + tn * 8 + (lane & 3) * 2;
            *(float2*)&cs[(size_t)row * CS_LD + col] =
                make_float2(cacc[tm][tn][0], cacc[tm][tn][1]);
            *(float2*)&cs[(size_t)(row + 8) * CS_LD + col] =
                make_float2(cacc[tm][tn][2], cacc[tm][tn][3]);
        }
    __syncthreads();

    // ---- epilogue: 2 threads per output row, 64 cols each ----
    const int row = tid >> 1, half = tid & 1;
    const float* crow = cs + (size_t)row * CS_LD + half * 64;

    if (EPI <= 1) {
        float rowb = (EPI == 1) ? bias[m0 + row] : 0.0f;
#pragma unroll
        for (int jj = 0; jj < 8; jj++) {
            float fv[8];
#pragma unroll
            for (int e = 0; e < 8; e++) {
                float f = crow[jj * 8 + e];
                f += (EPI == 0) ? sbias[half * 64 + jj * 8 + e] : rowb;
                fv[e] = f;
            }
            int ch = half * 8 + jj;              // 16B chunk 0..15
            int cc = ch >> 3, c8 = ch & 7;
            size_t toff = ((size_t)pm * NCout + (n0 >> 6) + cc) * 16384
                        + SWZ128((uint32_t)(row * 128 + c8 * 16));
            split8_store(fv, (char*)Ch + toff, (char*)Cl + toff);
        }
    } else {
        uint32_t mw[16];
        if (EPI == 2) {
            const uint4* m4 = (const uint4*)(maskT + (size_t)(m0 + row) * (size_t)ldc
                                             + n0 + half * 64);
#pragma unroll
            for (int q = 0; q < 4; q++) {
                uint4 u = m4[q];
                mw[q * 4] = u.x; mw[q * 4 + 1] = u.y; mw[q * 4 + 2] = u.z; mw[q * 4 + 3] = u.w;
            }
        }
        float* orow = Cf + (size_t)(m0 + row) * (size_t)ldc + n0 + half * 64;
#pragma unroll
        for (int jj = 0; jj < 16; jj++) {
            uint32_t o[4];
#pragma unroll
            for (int e = 0; e < 4; e++) {
                float f = crow[jj * 4 + e];
                if (EPI == 2) {
                    unsigned mb8 = (mw[jj] >> (e * 8)) & 0xFFu;
                    f = mb8 ? f * SCALE : NEG_MASKED;
                }
                o[e] = __float_as_uint(f);
            }
            *(uint4*)(orow + jj * 4) = make_uint4(o[0], o[1], o[2], o[3]);
        }
    }

    __syncthreads();
    if (tid == 0) { MBARRIER_INVAL(mb_full[0]); MBARRIER_INVAL(mb_full[1]); }
}

// ---------------------------------------------------------------------------
// Prep kernels
// ---------------------------------------------------------------------------
__global__ void detect_mask_kernel(const unsigned int* __restrict__ mw) {
    __shared__ int flag;
    if (threadIdx.x == 0) flag = 1;
    __syncthreads();
    bool byte_like = false;
    for (int i = threadIdx.x; i < 4096; i += 256)
        if (mw[i] > 1u) byte_like = true;
    if (byte_like) flag = 0;
    __syncthreads();
    if (threadIdx.x == 0) g_mask_is_word = flag;
}

__global__ void transpose_mask_kernel(const void* __restrict__ mask) {
    __shared__ unsigned char t[32][33];
    const int x0 = blockIdx.x * 32, z0 = blockIdx.y * 32;
    const int tx = threadIdx.x, ty = threadIdx.y;
    const int isw = g_mask_is_word;
#pragma unroll
    for (int i = 0; i < 4; i++) {
        int z = z0 + ty + i * 8;
        unsigned char v = isw
            ? (unsigned char)(((const int*)mask)[(size_t)z * LXC + x0 + tx] != 0)
            : (unsigned char)(((const unsigned char*)mask)[(size_t)z * LXC + x0 + tx] != 0);
        t[ty + i * 8][tx] = v;
    }
    __syncthreads();
#pragma unroll
    for (int i = 0; i < 4; i++)
        g_maskT[(size_t)(x0 + ty + i * 8) * LZC + z0 + tx] = t[tx][ty + i * 8];
}

__global__ __launch_bounds__(256)
void transpose_split_packed(const float* __restrict__ src, int C,
                            __nv_bfloat16* __restrict__ Ph,
                            __nv_bfloat16* __restrict__ Pl, int NC)
{
    __shared__ float sm[64][129];
    const int p = blockIdx.x, c = blockIdx.y;
    const int d0 = c * 64, x0 = p * 128;
    const int tid = threadIdx.x;
#pragma unroll
    for (int it = 0; it < 32; it++) {
        int idx = tid + it * 256;
        int r = idx >> 7, cc = idx & 127;
        sm[r][cc] = src[(size_t)(d0 + r) * C + x0 + cc];
    }
    __syncthreads();
    char* dh = (char*)Ph + ((size_t)p * NC + c) * 16384;
    char* dl = (char*)Pl + ((size_t)p * NC + c) * 16384;
#pragma unroll
    for (int it = 0; it < 4; it++) {
        int idx = tid + it * 256;
        int xl = idx >> 3, c8 = idx & 7;
        float fv[8];
#pragma unroll
        for (int j = 0; j < 8; j++) fv[j] = sm[c8 * 8 + j][xl];
        uint32_t sw = SWZ128((uint32_t)(xl * 128 + c8 * 16));
        split8_store(fv, dh + sw, dl + sw);
    }
}

__global__ __launch_bounds__(256)
void split_packed(const float* __restrict__ W, int C,
                  __nv_bfloat16* __restrict__ Ph, __nv_bfloat16* __restrict__ Pl, int NC)
{
    const int p = blockIdx.x, c = blockIdx.y;
    const int tid = threadIdx.x;
    char* dh = (char*)Ph + ((size_t)p * NC + c) * 16384;
    char* dl = (char*)Pl + ((size_t)p * NC + c) * 16384;
#pragma unroll
    for (int it = 0; it < 4; it++) {
        int idx = tid + it * 256;
        int r = idx >> 3, c8 = idx & 7;
        const float* s = W + (size_t)(p * 128 + r) * C + c * 64 + c8 * 8;
        float4 f0 = *(const float4*)s, f1 = *(const float4*)(s + 4);
        float fv[8] = {f0.x, f0.y, f0.z, f0.w, f1.x, f1.y, f1.z, f1.w};
        uint32_t sw = SWZ128((uint32_t)(r * 128 + c8 * 16));
        split8_store(fv, dh + sw, dl + sw);
    }
}

// row softmax of ST (LXC rows x LZC) + split-bf16 pack into B-operand tiles
__global__ __launch_bounds__(256)
void softmax_packed(const float* __restrict__ S,
                    __nv_bfloat16* __restrict__ Ah, __nv_bfloat16* __restrict__ Al)
{
    const int row = blockIdx.x, tid = threadIdx.x;
    const float* r = S + (size_t)row * LZC;
    __shared__ float red1[8], red2[8];

    float m = -1e30f;
    for (int i = tid; i < LZC; i += 256) m = fmaxf(m, r[i]);
#pragma unroll
    for (int o = 16; o; o >>= 1) m = fmaxf(m, __shfl_xor_sync(~0u, m, o));
    if ((tid & 31) == 0) red1[tid >> 5] = m;
    __syncthreads();
    m = red1[0];
#pragma unroll
    for (int j = 1; j < 8; j++) m = fmaxf(m, red1[j]);

    float sum = 0.0f;
    for (int i = tid; i < LZC; i += 256) sum += __expf(r[i] - m);
#pragma unroll
    for (int o = 16; o; o >>= 1) sum += __shfl_xor_sync(~0u, sum, o);
    if ((tid & 31) == 0) red2[tid >> 5] = sum;
    __syncthreads();
    sum = 0.0f;
#pragma unroll
    for (int j = 0; j < 8; j++) sum += red2[j];
    const float inv = 1.0f / sum;

    const int panel = row >> 7, rl = row & 127;
    char* bh = (char*)Ah + (size_t)panel * 64 * 16384;
    char* bl = (char*)Al + (size_t)panel * 64 * 16384;
#pragma unroll
    for (int ci = tid; ci < 512; ci += 256) {
        int tile = ci >> 3, c8 = ci & 7;
        float fv[8];
#pragma unroll
        for (int j = 0; j < 8; j++) fv[j] = __expf(r[ci * 8 + j] - m) * inv;
        size_t off = (size_t)tile * 16384 + SWZ128((uint32_t)(rl * 128 + c8 * 16));
        split8_store(fv, bh + off, bl + off);
    }
}

// ---------------------------------------------------------------------------
extern "C" void kernel_launch(void* const* d_in, const int* in_sizes, int n_in,
                              void* d_out, int out_size) {
    const float* X  = (const float*)d_in[0];
    const float* Z  = (const float*)d_in[1];
    const void* mask = d_in[2];
    const float* Wq = (const float*)d_in[3];
    const float* bq = (const float*)d_in[4];
    const float* Wk = (const float*)d_in[5];
    const float* bk = (const float*)d_in[6];
    const float* Wv = (const float*)d_in[7];
    const float* bv = (const float*)d_in[8];
    float* out = (float*)d_out;

    __nv_bfloat16 *XTh, *XTl, *ZTh, *ZTl, *Wqh, *Wql, *Wkh, *Wkl, *Wvh, *Wvl;
    __nv_bfloat16 *qTh, *qTl, *kTh, *kTl, *vh, *vl, *aTh, *aTl;
    float* ST; unsigned char* mT;
    cudaGetSymbolAddress((void**)&XTh, g_XTp_h); cudaGetSymbolAddress((void**)&XTl, g_XTp_l);
    cudaGetSymbolAddress((void**)&ZTh, g_ZTp_h); cudaGetSymbolAddress((void**)&ZTl, g_ZTp_l);
    cudaGetSymbolAddress((void**)&Wqh, g_Wqp_h); cudaGetSymbolAddress((void**)&Wql, g_Wqp_l);
    cudaGetSymbolAddress((void**)&Wkh, g_Wkp_h); cudaGetSymbolAddress((void**)&Wkl, g_Wkp_l);
    cudaGetSymbolAddress((void**)&Wvh, g_Wvp_h); cudaGetSymbolAddress((void**)&Wvl, g_Wvp_l);
    cudaGetSymbolAddress((void**)&qTh, g_qTp_h); cudaGetSymbolAddress((void**)&qTl, g_qTp_l);
    cudaGetSymbolAddress((void**)&kTh, g_kTp_h); cudaGetSymbolAddress((void**)&kTl, g_kTp_l);
    cudaGetSymbolAddress((void**)&vh,  g_vp_h);  cudaGetSymbolAddress((void**)&vl,  g_vp_l);
    cudaGetSymbolAddress((void**)&aTh, g_aTp_h); cudaGetSymbolAddress((void**)&aTl, g_aTp_l);
    cudaGetSymbolAddress((void**)&ST,  g_ST);    cudaGetSymbolAddress((void**)&mT,  g_maskT);

    cudaFuncSetAttribute(mma_gemm<0>, cudaFuncAttributeMaxDynamicSharedMemorySize, GEMM_SMEM);
    cudaFuncSetAttribute(mma_gemm<1>, cudaFuncAttributeMaxDynamicSharedMemorySize, GEMM_SMEM);
    cudaFuncSetAttribute(mma_gemm<2>, cudaFuncAttributeMaxDynamicSharedMemorySize, GEMM_SMEM);
    cudaFuncSetAttribute(mma_gemm<3>, cudaFuncAttributeMaxDynamicSharedMemorySize, GEMM_SMEM);

    detect_mask_kernel<<<1, 256>>>((const unsigned int*)mask);
    transpose_mask_kernel<<<dim3(LXC / 32, LZC / 32), dim3(32, 8)>>>(mask);
    transpose_split_packed<<<dim3(LXC / 128, DAC / 64), 256>>>(X, LXC, XTh, XTl, 16);
    transpose_split_packed<<<dim3(LZC / 128, DAC / 64), 256>>>(Z, LZC, ZTh, ZTl, 16);
    split_packed<<<dim3(DAC / 128, DAC / 64), 256>>>(Wq, DAC, Wqh, Wql, 16);
    split_packed<<<dim3(DAC / 128, DAC / 64), 256>>>(Wk, DAC, Wkh, Wkl, 16);
    split_packed<<<dim3(DAC / 128, DAC / 64), 256>>>(Wv, DAC, Wvh, Wvl, 16);

    // qT (lx,da) = XT @ Wq^T + bq[n] ; kT (lz,da) = ZT @ Wk^T + bk[n]
    mma_gemm<0><<<dim3(8, 32), 256, GEMM_SMEM>>>(XTh, XTl, Wqh, Wql, 16,
        nullptr, qTh, qTl, 16, 0, bq, nullptr);
    mma_gemm<0><<<dim3(8, 32), 256, GEMM_SMEM>>>(ZTh, ZTl, Wkh, Wkl, 16,
        nullptr, kTh, kTl, 16, 0, bk, nullptr);
    // v (do,lz) = Wv @ ZT^T + bv[m]
    mma_gemm<1><<<dim3(32, 8), 256, GEMM_SMEM>>>(Wvh, Wvl, ZTh, ZTl, 16,
        nullptr, vh, vl, 64, 0, bv, nullptr);
    // ST (lx,lz) = qT @ kT^T, mask+scale epilogue
    mma_gemm<2><<<dim3(32, 32), 256, GEMM_SMEM>>>(qTh, qTl, kTh, kTl, 16,
        ST, nullptr, nullptr, 0, LZC, nullptr, mT);
    // softmax over z per row + packed split attnT
    softmax_packed<<<LXC, 256>>>(ST, aTh, aTl);
    // out (do,lx) = v @ attn
    mma_gemm<3><<<dim3(32, 8), 256, GEMM_SMEM>>>(vh, vl, aTh, aTl, 64,
        out, nullptr, nullptr, 0, LXC, nullptr, nullptr);
}

// round 5
// speedup vs baseline: 2.8405x; 1.0707x over previous
#include <cuda_runtime.h>
#include <cuda_bf16.h>
#include <cstdint>

#define LXC 4096
#define LZC 4096
#define DAC 1024
#define SCALE 0.03125f        // 1/sqrt(1024)
#define NEG_MASKED (-31.25f)  // -1000 * SCALE (fill applied BEFORE scaling)

// ---------------------------------------------------------------------------
// Device-global scratch. Packed operands: SW128-swizzled smem tile images,
// tiles of 128 rows x 64 bf16 cols (16384 B); tile (panel p, chunk c) at
// offset (p*NC + c)*16384.
// ---------------------------------------------------------------------------
__device__ __align__(256) __nv_bfloat16 g_XTp_h[(size_t)LXC * DAC], g_XTp_l[(size_t)LXC * DAC];
__device__ __align__(256) __nv_bfloat16 g_ZTp_h[(size_t)LZC * DAC], g_ZTp_l[(size_t)LZC * DAC];
__device__ __align__(256) __nv_bfloat16 g_Wqp_h[(size_t)DAC * DAC], g_Wqp_l[(size_t)DAC * DAC];
__device__ __align__(256) __nv_bfloat16 g_Wkp_h[(size_t)DAC * DAC], g_Wkp_l[(size_t)DAC * DAC];
__device__ __align__(256) __nv_bfloat16 g_Wvp_h[(size_t)DAC * DAC], g_Wvp_l[(size_t)DAC * DAC];
__device__ __align__(256) __nv_bfloat16 g_qTp_h[(size_t)LXC * DAC], g_qTp_l[(size_t)LXC * DAC];
__device__ __align__(256) __nv_bfloat16 g_kTp_h[(size_t)LZC * DAC], g_kTp_l[(size_t)LZC * DAC];
__device__ __align__(256) __nv_bfloat16 g_vp_h[(size_t)DAC * LZC],  g_vp_l[(size_t)DAC * LZC];
__device__ __align__(256) __nv_bfloat16 g_aTp_h[(size_t)LXC * LZC], g_aTp_l[(size_t)LXC * LZC];
__device__ __align__(256) float         g_ST[(size_t)LXC * LZC];
__device__ __align__(256) unsigned char g_maskT[(size_t)LXC * LZC];
__device__ int g_mask_is_word;

// ---------------------------------------------------------------------------
// PTX helpers (non-"a" sm_90 baseline features only)
// ---------------------------------------------------------------------------
__device__ __forceinline__ uint32_t elect_one_pred() {
    uint32_t pred;
    asm volatile("{\n\t.reg .pred p;\n\t"
                 "elect.sync _|p, 0xFFFFFFFF;\n\t"
                 "selp.b32 %0, 1, 0, p;\n\t}" : "=r"(pred));
    return pred;
}
__device__ __forceinline__ uint32_t smem_u32(const void* p) {
    uint32_t a;
    asm("{ .reg .u64 t; cvta.to.shared.u64 t, %1; cvt.u32.u64 %0, t; }" : "=r"(a) : "l"(p));
    return a;
}

#define MBARRIER_INIT(mb, cnt) \
    asm volatile("mbarrier.init.shared.b64 [%0], %1;" \
                 :: "r"((uint32_t)(mb)), "r"((uint32_t)(cnt)) : "memory")
#define MBARRIER_INVAL(mb) \
    asm volatile("mbarrier.inval.shared.b64 [%0];" :: "r"((uint32_t)(mb)) : "memory")
#define MBARRIER_EXPECT_TX(mb, tx) \
    asm volatile("mbarrier.arrive.expect_tx.shared.b64 _, [%0], %1;" \
                 :: "r"((uint32_t)(mb)), "r"((uint32_t)(tx)) : "memory")

#define MBARRIER_WAIT_PARITY(mb, par) do {                                        \
    uint32_t _m = (uint32_t)(mb); uint32_t _p = (uint32_t)(par); uint32_t _d;     \
    asm volatile("{\n\t.reg .pred p;\n\t"                                         \
        "mbarrier.try_wait.parity.acquire.cta.shared::cta.b64 p, [%1], %2;\n\t"   \
        "selp.b32 %0, 1, 0, p;\n\t}" : "=r"(_d) : "r"(_m), "r"(_p) : "memory");   \
    if (!_d) {                                                                    \
        asm volatile("{\n\t.reg .pred P1;\n\t"                                    \
            "WAIT_LOOP_%=:\n\t"                                                   \
            "mbarrier.try_wait.parity.acquire.cta.shared::cta.b64 P1, [%0], %1, 0x989680;\n\t" \
            "@P1 bra.uni WAIT_DONE_%=;\n\t"                                       \
            "bra.uni WAIT_LOOP_%=;\n\t"                                           \
            "WAIT_DONE_%=:\n\t}" :: "r"(_m), "r"(_p) : "memory");                 \
    }                                                                             \
} while (0)

#define SWZ128(bo) ((bo) ^ (((bo) >> 3) & 0x70))

__device__ __forceinline__ void bulk_g2s(uint32_t dst, const void* src,
                                         uint32_t bytes, uint32_t mbar) {
    asm volatile(
        "cp.async.bulk.shared::cluster.global.mbarrier::complete_tx::bytes [%0], [%1], %2, [%3];"
        :: "r"(dst), "l"(src), "r"(bytes), "r"(mbar) : "memory");
}

__device__ __forceinline__ void ldsm4(uint32_t* d, uint32_t addr) {
    asm volatile("ldmatrix.sync.aligned.m8n8.x4.shared.b16 {%0,%1,%2,%3}, [%4];"
                 : "=r"(d[0]), "=r"(d[1]), "=r"(d[2]), "=r"(d[3]) : "r"(addr));
}

__device__ __forceinline__ void mma16816(float* c, const uint32_t* a, const uint32_t* b) {
    asm volatile("mma.sync.aligned.m16n8k16.row.col.f32.bf16.bf16.f32 "
        "{%0,%1,%2,%3}, {%4,%5,%6,%7}, {%8,%9}, {%0,%1,%2,%3};"
        : "+f"(c[0]), "+f"(c[1]), "+f"(c[2]), "+f"(c[3])
        : "r"(a[0]), "r"(a[1]), "r"(a[2]), "r"(a[3]), "r"(b[0]), "r"(b[1]));
}

// split fp32 -> bf16 hi/lo; pack 8 values; store 16B hi + 16B lo
__device__ __forceinline__ void split8_store(const float* fv, char* dh, char* dl) {
    uint32_t hw[4], lw[4];
#pragma unroll
    for (int j = 0; j < 4; j++) {
        __nv_bfloat16 h0 = __float2bfloat16(fv[2 * j]);
        __nv_bfloat16 h1 = __float2bfloat16(fv[2 * j + 1]);
        __nv_bfloat16 l0 = __float2bfloat16(fv[2 * j]     - __bfloat162float(h0));
        __nv_bfloat16 l1 = __float2bfloat16(fv[2 * j + 1] - __bfloat162float(h1));
        hw[j] = (uint32_t)__bfloat16_as_ushort(h0) | ((uint32_t)__bfloat16_as_ushort(h1) << 16);
        lw[j] = (uint32_t)__bfloat16_as_ushort(l0) | ((uint32_t)__bfloat16_as_ushort(l1) << 16);
    }
    *(uint4*)dh = make_uint4(hw[0], hw[1], hw[2], hw[3]);
    *(uint4*)dl = make_uint4(lw[0], lw[1], lw[2], lw[3]);
}

// ---------------------------------------------------------------------------
// Shared HMMA mainloop: 128x128 CTA tile, K-chunk 64, 3 smem stages (64KB),
// 8 warps (warp tile 32x64), 3-product bf16 split, product-major ordering.
// Stage s barrier at sb+16+8s. Stages at stg + s*65536.
// ---------------------------------------------------------------------------
#define GEMM_SMEM 200704
#define CS_LD 132

__device__ __forceinline__ void hmma_mainloop(
    const char* aHb, const char* aLb, const char* bHb, const char* bLb,
    int NC, uint32_t sb, uint32_t stg, int tid, int wid, int lane,
    float (&cacc)[2][8][4])
{
    int leader = 0;
    if (wid == 0) leader = elect_one_pred();

    const int mbase = (wid & 3) * 32;
    const int nbase = (wid >> 2) * 64;
    const int r8 = lane & 7, g = lane >> 3;
    uint32_t arow[2], brow[4];
#pragma unroll
    for (int tm = 0; tm < 2; tm++)
        arow[tm] = (uint32_t)(mbase + tm * 16 + (g & 1) * 8 + r8) * 128u;
#pragma unroll
    for (int tp = 0; tp < 4; tp++)
        brow[tp] = (uint32_t)(nbase + tp * 16 + (g >> 1) * 8 + r8) * 128u;
    const uint32_t kbA = (uint32_t)(g >> 1) * 16u;
    const uint32_t kbB = (uint32_t)(g & 1) * 16u;

    auto prefetch = [&](int c, int s) {
        uint32_t mb = sb + 16 + 8 * s;
        MBARRIER_EXPECT_TX(mb, 65536u);
        uint32_t d = stg + (uint32_t)s * 65536u;
        size_t off = (size_t)c * 16384;
        bulk_g2s(d,          aHb + off, 16384u, mb);
        bulk_g2s(d + 16384u, aLb + off, 16384u, mb);
        bulk_g2s(d + 32768u, bHb + off, 16384u, mb);
        bulk_g2s(d + 49152u, bLb + off, 16384u, mb);
    };
    if (leader) { prefetch(0, 0); prefetch(1, 1); prefetch(2, 2); }

    for (int c = 0; c < NC; c++) {
        const int u = c / 3;
        const int s = c - u * 3;
        MBARRIER_WAIT_PARITY(sb + 16 + 8 * s, u & 1);
        const uint32_t base = stg + (uint32_t)s * 65536u;

#pragma unroll
        for (int ks = 0; ks < 4; ks++) {
            const uint32_t kb = (uint32_t)ks * 32u;
            uint32_t ah[2][4], al[2][4], bh[8][2], bl[8][2];
#pragma unroll
            for (int tm = 0; tm < 2; tm++) {
                uint32_t sw = SWZ128(arow[tm] + kb + kbA);
                ldsm4(ah[tm], base + sw);
                ldsm4(al[tm], base + 16384u + sw);
            }
#pragma unroll
            for (int tp = 0; tp < 4; tp++) {
                uint32_t sw = SWZ128(brow[tp] + kb + kbB);
                uint32_t t[4];
                ldsm4(t, base + 32768u + sw);
                bh[2 * tp][0] = t[0]; bh[2 * tp][1] = t[1];
                bh[2 * tp + 1][0] = t[2]; bh[2 * tp + 1][1] = t[3];
                ldsm4(t, base + 49152u + sw);
                bl[2 * tp][0] = t[0]; bl[2 * tp][1] = t[1];
                bl[2 * tp + 1][0] = t[2]; bl[2 * tp + 1][1] = t[3];
            }
            // product-major: independent accumulators within each pass
#pragma unroll
            for (int tm = 0; tm < 2; tm++)
#pragma unroll
                for (int tn = 0; tn < 8; tn++) mma16816(cacc[tm][tn], ah[tm], bh[tn]);
#pragma unroll
            for (int tm = 0; tm < 2; tm++)
#pragma unroll
                for (int tn = 0; tn < 8; tn++) mma16816(cacc[tm][tn], ah[tm], bl[tn]);
#pragma unroll
            for (int tm = 0; tm < 2; tm++)
#pragma unroll
                for (int tn = 0; tn < 8; tn++) mma16816(cacc[tm][tn], al[tm], bh[tn]);
        }
        __syncthreads();
        if (leader && c + 3 < NC) prefetch(c + 3, s);
    }
}

__device__ __forceinline__ void stage_acc(float* cs, float (&cacc)[2][8][4],
                                          int wid, int lane) {
    const int mbase = (wid & 3) * 32, nbase = (wid >> 2) * 64;
#pragma unroll
    for (int tm = 0; tm < 2; tm++)
#pragma unroll
        for (int tn = 0; tn < 8; tn++) {
            int row = mbase + tm * 16 + (lane >> 2);
            int col = nbase + tn * 8 + (lane & 3) * 2;
            *(float2*)&cs[(size_t)row * CS_LD + col] =
                make_float2(cacc[tm][tn][0], cacc[tm][tn][1]);
            *(float2*)&cs[(size_t)(row + 8) * CS_LD + col] =
                make_float2(cacc[tm][tn][2], cacc[tm][tn][3]);
        }
}

// ---------------------------------------------------------------------------
// Fused q/k/v projection GEMM: z = 0 -> qT, 1 -> kT, 2 -> v (pm/pn swapped).
// Output: packed split-bf16 tiles.
// ---------------------------------------------------------------------------
__global__ __launch_bounds__(256, 1)
void proj_gemm(const float* __restrict__ bq, const float* __restrict__ bk,
               const float* __restrict__ bv)
{
    extern __shared__ char smem[];
    const uint32_t sb = smem_u32(smem);
    const int tid = threadIdx.x, wid = tid >> 5, lane = tid & 31;
    const int z = blockIdx.z;
    const int pm = (z == 2) ? blockIdx.x : blockIdx.y;
    const int pn = (z == 2) ? blockIdx.y : blockIdx.x;
    const uint32_t stg = (sb + 2048 + 1023) & ~1023u;
    char* stgp = smem + (stg - sb);
    float* sbias = (float*)(smem + 512);

    const char *aH, *aL, *bH, *bL;
    __nv_bfloat16 *Ch, *Cl;
    const float* bias;
    int NCout;
    if (z == 0) {
        aH = (const char*)g_XTp_h; aL = (const char*)g_XTp_l;
        bH = (const char*)g_Wqp_h; bL = (const char*)g_Wqp_l;
        Ch = g_qTp_h; Cl = g_qTp_l; bias = bq; NCout = 16;
    } else if (z == 1) {
        aH = (const char*)g_ZTp_h; aL = (const char*)g_ZTp_l;
        bH = (const char*)g_Wkp_h; bL = (const char*)g_Wkp_l;
        Ch = g_kTp_h; Cl = g_kTp_l; bias = bk; NCout = 16;
    } else {
        aH = (const char*)g_Wvp_h; aL = (const char*)g_Wvp_l;
        bH = (const char*)g_ZTp_h; bL = (const char*)g_ZTp_l;
        Ch = g_vp_h; Cl = g_vp_l; bias = bv; NCout = 64;
    }

    if (tid == 0) {
        MBARRIER_INIT(sb + 16, 1); MBARRIER_INIT(sb + 24, 1); MBARRIER_INIT(sb + 32, 1);
    }
    if (z < 2 && tid < 128) sbias[tid] = bias[pn * 128 + tid];
    __syncthreads();

    float cacc[2][8][4];
#pragma unroll
    for (int i = 0; i < 2; i++)
#pragma unroll
        for (int j = 0; j < 8; j++)
#pragma unroll
            for (int e = 0; e < 4; e++) cacc[i][j][e] = 0.0f;

    hmma_mainloop(aH + (size_t)pm * 16 * 16384, aL + (size_t)pm * 16 * 16384,
                  bH + (size_t)pn * 16 * 16384, bL + (size_t)pn * 16 * 16384,
                  16, sb, stg, tid, wid, lane, cacc);

    float* cs = (float*)stgp;
    stage_acc(cs, cacc, wid, lane);
    __syncthreads();

    const int m0 = pm * 128, n0 = pn * 128;
    const int rbase = (tid >> 4) * 8, tile = (tid >> 3) & 1, c8 = tid & 7;
#pragma unroll
    for (int it = 0; it < 8; it++) {
        int row = rbase + it;
        float rowb = (z == 2) ? bias[m0 + row] : 0.0f;
        float fv[8];
        const float* src = cs + (size_t)row * CS_LD + tile * 64 + c8 * 8;
        float4 f0 = *(const float4*)src, f1 = *(const float4*)(src + 4);
        float raw[8] = {f0.x, f0.y, f0.z, f0.w, f1.x, f1.y, f1.z, f1.w};
#pragma unroll
        for (int j = 0; j < 8; j++)
            fv[j] = raw[j] + ((z < 2) ? sbias[tile * 64 + c8 * 8 + j] : rowb);
        size_t toff = ((size_t)pm * NCout + (n0 >> 6) + tile) * 16384
                    + SWZ128((uint32_t)(row * 128 + c8 * 16));
        split8_store(fv, (char*)Ch + toff, (char*)Cl + toff);
    }
    __syncthreads();
    if (tid == 0) {
        MBARRIER_INVAL(sb + 16); MBARRIER_INVAL(sb + 24); MBARRIER_INVAL(sb + 32);
    }
}

// ---------------------------------------------------------------------------
// Score GEMM: ST[x,z] = qT @ kT^T with fused mask+scale epilogue (fp32 out).
// ---------------------------------------------------------------------------
__global__ __launch_bounds__(256, 1)
void score_gemm()
{
    extern __shared__ char smem[];
    const uint32_t sb = smem_u32(smem);
    const int tid = threadIdx.x, wid = tid >> 5, lane = tid & 31;
    const int pm = blockIdx.y, pn = blockIdx.x;
    const uint32_t stg = (sb + 2048 + 1023) & ~1023u;
    char* stgp = smem + (stg - sb);

    if (tid == 0) {
        MBARRIER_INIT(sb + 16, 1); MBARRIER_INIT(sb + 24, 1); MBARRIER_INIT(sb + 32, 1);
    }
    __syncthreads();

    float cacc[2][8][4];
#pragma unroll
    for (int i = 0; i < 2; i++)
#pragma unroll
        for (int j = 0; j < 8; j++)
#pragma unroll
            for (int e = 0; e < 4; e++) cacc[i][j][e] = 0.0f;

    hmma_mainloop((const char*)g_qTp_h + (size_t)pm * 16 * 16384,
                  (const char*)g_qTp_l + (size_t)pm * 16 * 16384,
                  (const char*)g_kTp_h + (size_t)pn * 16 * 16384,
                  (const char*)g_kTp_l + (size_t)pn * 16 * 16384,
                  16, sb, stg, tid, wid, lane, cacc);

    float* cs = (float*)stgp;
    stage_acc(cs, cacc, wid, lane);
    __syncthreads();

    const int m0 = pm * 128, n0 = pn * 128;
    const int chunk = tid & 31, wrow = tid >> 5;
#pragma unroll
    for (int it = 0; it < 16; it++) {
        int row = wrow * 16 + it;
        uint32_t mw = *(const uint32_t*)(g_maskT + (size_t)(m0 + row) * LZC + n0 + chunk * 4);
        const float* src = cs + (size_t)row * CS_LD + chunk * 4;
        float4 f = *(const float4*)src;
        float o[4] = {f.x, f.y, f.z, f.w};
        uint32_t w[4];
#pragma unroll
        for (int e = 0; e < 4; e++) {
            unsigned mb8 = (mw >> (e * 8)) & 0xFFu;
            w[e] = __float_as_uint(mb8 ? o[e] * SCALE : NEG_MASKED);
        }
        *(uint4*)(g_ST + (size_t)(m0 + row) * LZC + n0 + chunk * 4) =
            make_uint4(w[0], w[1], w[2], w[3]);
    }
    __syncthreads();
    if (tid == 0) {
        MBARRIER_INVAL(sb + 16); MBARRIER_INVAL(sb + 24); MBARRIER_INVAL(sb + 32);
    }
}

// ---------------------------------------------------------------------------
// Out GEMM: out[d,x] = v @ attn (K = lz = 4096, NC = 64), plain fp32 out.
// ---------------------------------------------------------------------------
__global__ __launch_bounds__(256, 1)
void out_gemm(float* __restrict__ out)
{
    extern __shared__ char smem[];
    const uint32_t sb = smem_u32(smem);
    const int tid = threadIdx.x, wid = tid >> 5, lane = tid & 31;
    const int pm = blockIdx.y, pn = blockIdx.x;
    const uint32_t stg = (sb + 2048 + 1023) & ~1023u;
    char* stgp = smem + (stg - sb);

    if (tid == 0) {
        MBARRIER_INIT(sb + 16, 1); MBARRIER_INIT(sb + 24, 1); MBARRIER_INIT(sb + 32, 1);
    }
    __syncthreads();

    float cacc[2][8][4];
#pragma unroll
    for (int i = 0; i < 2; i++)
#pragma unroll
        for (int j = 0; j < 8; j++)
#pragma unroll
            for (int e = 0; e < 4; e++) cacc[i][j][e] = 0.0f;

    hmma_mainloop((const char*)g_vp_h + (size_t)pm * 64 * 16384,
                  (const char*)g_vp_l + (size_t)pm * 64 * 16384,
                  (const char*)g_aTp_h + (size_t)pn * 64 * 16384,
                  (const char*)g_aTp_l + (size_t)pn * 64 * 16384,
                  64, sb, stg, tid, wid, lane, cacc);

    float* cs = (float*)stgp;
    stage_acc(cs, cacc, wid, lane);
    __syncthreads();

    const int m0 = pm * 128, n0 = pn * 128;
    const int chunk = tid & 31, wrow = tid >> 5;
#pragma unroll
    for (int it = 0; it < 16; it++) {
        int row = wrow * 16 + it;
        const float* src = cs + (size_t)row * CS_LD + chunk * 4;
        float4 f = *(const float4*)src;
        *(float4*)(out + (size_t)(m0 + row) * LXC + n0 + chunk * 4) = f;
    }
    __syncthreads();
    if (tid == 0) {
        MBARRIER_INVAL(sb + 16); MBARRIER_INVAL(sb + 24); MBARRIER_INVAL(sb + 32);
    }
}

// ---------------------------------------------------------------------------
// Prep kernels
// ---------------------------------------------------------------------------
__global__ void detect_mask_kernel(const unsigned int* __restrict__ mw) {
    __shared__ int flag;
    if (threadIdx.x == 0) flag = 1;
    __syncthreads();
    bool byte_like = false;
    for (int i = threadIdx.x; i < 4096; i += 256)
        if (mw[i] > 1u) byte_like = true;
    if (byte_like) flag = 0;
    __syncthreads();
    if (threadIdx.x == 0) g_mask_is_word = flag;
}

__global__ void transpose_mask_kernel(const void* __restrict__ mask) {
    __shared__ unsigned char t[32][33];
    const int x0 = blockIdx.x * 32, z0 = blockIdx.y * 32;
    const int tx = threadIdx.x, ty = threadIdx.y;
    const int isw = g_mask_is_word;
#pragma unroll
    for (int i = 0; i < 4; i++) {
        int z = z0 + ty + i * 8;
        unsigned char v = isw
            ? (unsigned char)(((const int*)mask)[(size_t)z * LXC + x0 + tx] != 0)
            : (unsigned char)(((const unsigned char*)mask)[(size_t)z * LXC + x0 + tx] != 0);
        t[ty + i * 8][tx] = v;
    }
    __syncthreads();
#pragma unroll
    for (int i = 0; i < 4; i++)
        g_maskT[(size_t)(x0 + ty + i * 8) * LZC + z0 + tx] = t[tx][ty + i * 8];
}

// transpose + split + pack X (z=0) and Z (z=1). grid (32, 16, 2).
__global__ __launch_bounds__(256)
void transpose_split_packed(const float* __restrict__ X, const float* __restrict__ Z)
{
    __shared__ float sm[64][129];
    const float* src = blockIdx.z ? Z : X;
    __nv_bfloat16* Ph = blockIdx.z ? g_ZTp_h : g_XTp_h;
    __nv_bfloat16* Pl = blockIdx.z ? g_ZTp_l : g_XTp_l;
    const int p = blockIdx.x, c = blockIdx.y;
    const int d0 = c * 64, x0 = p * 128;
    const int tid = threadIdx.x;
#pragma unroll
    for (int it = 0; it < 32; it++) {
        int idx = tid + it * 256;
        int r = idx >> 7, cc = idx & 127;
        sm[r][cc] = src[(size_t)(d0 + r) * 4096 + x0 + cc];
    }
    __syncthreads();
    char* dh = (char*)Ph + ((size_t)p * 16 + c) * 16384;
    char* dl = (char*)Pl + ((size_t)p * 16 + c) * 16384;
#pragma unroll
    for (int it = 0; it < 4; it++) {
        int idx = tid + it * 256;
        int xl = idx >> 3, c8 = idx & 7;
        float fv[8];
#pragma unroll
        for (int j = 0; j < 8; j++) fv[j] = sm[c8 * 8 + j][xl];
        uint32_t sw = SWZ128((uint32_t)(xl * 128 + c8 * 16));
        split8_store(fv, dh + sw, dl + sw);
    }
}

// split + pack Wq (z=0), Wk (z=1), Wv (z=2). grid (8, 16, 3).
__global__ __launch_bounds__(256)
void split_packed(const float* __restrict__ Wq, const float* __restrict__ Wk,
                  const float* __restrict__ Wv)
{
    const int z = blockIdx.z;
    const float* W = (z == 0) ? Wq : ((z == 1) ? Wk : Wv);
    __nv_bfloat16* Ph = (z == 0) ? g_Wqp_h : ((z == 1) ? g_Wkp_h : g_Wvp_h);
    __nv_bfloat16* Pl = (z == 0) ? g_Wqp_l : ((z == 1) ? g_Wkp_l : g_Wvp_l);
    const int p = blockIdx.x, c = blockIdx.y;
    const int tid = threadIdx.x;
    char* dh = (char*)Ph + ((size_t)p * 16 + c) * 16384;
    char* dl = (char*)Pl + ((size_t)p * 16 + c) * 16384;
#pragma unroll
    for (int it = 0; it < 4; it++) {
        int idx = tid + it * 256;
        int r = idx >> 3, c8 = idx & 7;
        const float* s = W + (size_t)(p * 128 + r) * DAC + c * 64 + c8 * 8;
        float4 f0 = *(const float4*)s, f1 = *(const float4*)(s + 4);
        float fv[8] = {f0.x, f0.y, f0.z, f0.w, f1.x, f1.y, f1.z, f1.w};
        uint32_t sw = SWZ128((uint32_t)(r * 128 + c8 * 16));
        split8_store(fv, dh + sw, dl + sw);
    }
}

// single-pass row softmax of g_ST + packed split-bf16 attnT tiles.
// 256 threads/row; each thread owns 16 contiguous values in registers.
__global__ __launch_bounds__(256)
void softmax_packed()
{
    const int row = blockIdx.x, tid = threadIdx.x;
    const float4* r4 = (const float4*)(g_ST + (size_t)row * LZC);
    __shared__ float redm[8], reds[8];

    float v[16];
#pragma unroll
    for (int q = 0; q < 4; q++) {
        float4 f = r4[tid * 4 + q];
        v[q * 4 + 0] = f.x; v[q * 4 + 1] = f.y; v[q * 4 + 2] = f.z; v[q * 4 + 3] = f.w;
    }
    float m = v[0];
#pragma unroll
    for (int j = 1; j < 16; j++) m = fmaxf(m, v[j]);
#pragma unroll
    for (int o = 16; o; o >>= 1) m = fmaxf(m, __shfl_xor_sync(~0u, m, o));
    if ((tid & 31) == 0) redm[tid >> 5] = m;
    __syncthreads();
    m = redm[0];
#pragma unroll
    for (int j = 1; j < 8; j++) m = fmaxf(m, redm[j]);

    float e[16];
    float sum = 0.0f;
#pragma unroll
    for (int j = 0; j < 16; j++) { e[j] = __expf(v[j] - m); sum += e[j]; }
#pragma unroll
    for (int o = 16; o; o >>= 1) sum += __shfl_xor_sync(~0u, sum, o);
    if ((tid & 31) == 0) reds[tid >> 5] = sum;
    __syncthreads();
    sum = 0.0f;
#pragma unroll
    for (int j = 0; j < 8; j++) sum += reds[j];
    const float inv = 1.0f / sum;

    const int panel = row >> 7, rl = row & 127;
    char* bh = (char*)g_aTp_h + (size_t)panel * 64 * 16384;
    char* bl = (char*)g_aTp_l + (size_t)panel * 64 * 16384;
#pragma unroll
    for (int half = 0; half < 2; half++) {
        float w[8];
#pragma unroll
        for (int j = 0; j < 8; j++) w[j] = e[half * 8 + j] * inv;
        int ci = 2 * tid + half;
        int tile = ci >> 3, c8 = ci & 7;
        size_t off = (size_t)tile * 16384 + SWZ128((uint32_t)(rl * 128 + c8 * 16));
        split8_store(w, bh + off, bl + off);
    }
}

// ---------------------------------------------------------------------------
extern "C" void kernel_launch(void* const* d_in, const int* in_sizes, int n_in,
                              void* d_out, int out_size) {
    const float* X  = (const float*)d_in[0];
    const float* Z  = (const float*)d_in[1];
    const void* mask = d_in[2];
    const float* Wq = (const float*)d_in[3];
    const float* bq = (const float*)d_in[4];
    const float* Wk = (const float*)d_in[5];
    const float* bk = (const float*)d_in[6];
    const float* Wv = (const float*)d_in[7];
    const float* bv = (const float*)d_in[8];
    float* out = (float*)d_out;

    cudaFuncSetAttribute(proj_gemm,  cudaFuncAttributeMaxDynamicSharedMemorySize, GEMM_SMEM);
    cudaFuncSetAttribute(score_gemm, cudaFuncAttributeMaxDynamicSharedMemorySize, GEMM_SMEM);
    cudaFuncSetAttribute(out_gemm,   cudaFuncAttributeMaxDynamicSharedMemorySize, GEMM_SMEM);

    detect_mask_kernel<<<1, 256>>>((const unsigned int*)mask);
    transpose_mask_kernel<<<dim3(LXC / 32, LZC / 32), dim3(32, 8)>>>(mask);
    transpose_split_packed<<<dim3(32, 16, 2), 256>>>(X, Z);
    split_packed<<<dim3(8, 16, 3), 256>>>(Wq, Wk, Wv);

    proj_gemm<<<dim3(8, 32, 3), 256, GEMM_SMEM>>>(bq, bk, bv);
    score_gemm<<<dim3(32, 32), 256, GEMM_SMEM>>>();
    softmax_packed<<<LXC, 256>>>();
    out_gemm<<<dim3(32, 8), 256, GEMM_SMEM>>>(out);
}